// round 4
// baseline (speedup 1.0000x reference)
#include <cuda_runtime.h>
#include <cuda_bf16.h>

#define H      488
#define AW     484          // H - 5 + 1
#define KCL    6
#define NB     32
#define ITERS  10
#define SEG    121          // 484 = 4 * 121 windows per row
#define NSEG   4
#define NPART  (AW * NSEG)  // 1936 partials per batch
#define CR0    16           // rows per scan0 chunk
#define NCH0   31           // ceil(484/16)
#define NE4    (H * H / 4)  // 59536 float4 per batch
#define NCHE   32
#define CE4    1861         // ceil(59536/32)
#define RW     4            // warps per cluster in refine

// Scratch (allocation-free: __device__ globals)
__device__ float g_pv[NB * NPART];          // per-(row,seg) argmax value
__device__ int   g_pi[NB * NPART];          // per-(row,seg) argmax flat window idx
__device__ int   g_wr[NB * KCL], g_wc[NB * KCL];
__device__ float g_maxv[NB * KCL];
__device__ int   g_eqmin[NB * KCL];         // first-occurrence flat hm index

__device__ __forceinline__ void better(float v, int i, float& bv, int& bi) {
    if (v > bv || (v == bv && i < bi)) { bv = v; bi = i; }
}

// ---------------------------------------------------------------------------
// scan0: input -> initial argmax partials (colsum lives only in smem).
// grid (NB, 31) x 256.
// ---------------------------------------------------------------------------
__global__ __launch_bounds__(256)
void scan0_kernel(const float* __restrict__ in) {
    const int b = blockIdx.x, cb = blockIdx.y, tid = threadIdx.x;
    const float* src = in + (size_t)b * H * H;

    __shared__ float s_cs[CR0][H];

    const int R0 = CR0 * cb, R1 = min(AW, R0 + CR0);

    // column 5-sums for rows [R0, R1): left-assoc register ring
    for (int j = tid; j < H; j += 256) {
        float w0 = src[(R0 + 0) * H + j], w1 = src[(R0 + 1) * H + j],
              w2 = src[(R0 + 2) * H + j], w3 = src[(R0 + 3) * H + j], w4;
        for (int i = R0; i < R1; i++) {
            w4 = src[(i + 4) * H + j];
            s_cs[i - R0][j] = w0 + w1 + w2 + w3 + w4;
            w0 = w1; w1 = w2; w2 = w3; w3 = w4;
        }
    }
    __syncthreads();

    // partials: 64 (row,seg) pairs, 4 sub-threads each
    const int pair = tid >> 2, sub = tid & 3;
    const int lr = pair >> 2, sg = pair & 3;
    const int nrows = R1 - R0;

    float bv = -1.0f; int bi = 0x7fffffff;
    if (lr < nrows) {
        const float* row = s_cs[lr];
        const int jbeg = sg * SEG;
        for (int j = jbeg + sub; j < jbeg + SEG; j += 4) {
            float v = row[j] + row[j + 1] + row[j + 2] + row[j + 3] + row[j + 4];
            better(v, (R0 + lr) * AW + j, bv, bi);
        }
    }
    #pragma unroll
    for (int off = 2; off; off >>= 1) {
        float ov = __shfl_down_sync(0xffffffffu, bv, off);
        int   oi = __shfl_down_sync(0xffffffffu, bi, off);
        better(ov, oi, bv, bi);
    }
    if (sub == 0 && lr < nrows) {
        g_pv[b * NPART + (R0 + lr) * NSEG + sg] = bv;
        g_pi[b * NPART + (R0 + lr) * NSEG + sg] = bi;
    }
}

// ---------------------------------------------------------------------------
// final6: all 6 greedy extractions in one kernel. grid NB x 256.
// Partials in smem. No heatmap mutation, no colsum array: values are
// recomputed from src with window-coverage zeroing (bit-exact left-assoc).
// ---------------------------------------------------------------------------
__global__ __launch_bounds__(256)
void final6_kernel(const float* __restrict__ in) {
    const int b = blockIdx.x, tid = threadIdx.x;
    const int warp = tid >> 5, lane = tid & 31;
    const float* src = in + (size_t)b * H * H;

    __shared__ float s_pv[NPART];
    __shared__ int   s_pi[NPART];
    __shared__ float s_rv[8];
    __shared__ int   s_ri[8];
    __shared__ float s_win[25];
    __shared__ int   s_wr[KCL], s_wc[KCL];
    __shared__ float s_mv[KCL];
    __shared__ int   s_r, s_c;
    __shared__ float s_csbuf[8][126];   // per-warp colsum segment scratch

    for (int i = tid; i < NPART; i += 256) {
        s_pv[i] = g_pv[b * NPART + i];
        s_pi[i] = g_pi[b * NPART + i];
    }
    if (tid < KCL) g_eqmin[b * KCL + tid] = 0x7fffffff;   // init for eq pass
    __syncthreads();

    for (int it = 0; it < KCL; it++) {
        // ---- A: global argmax over 1936 smem partials (shuffle tree)
        {
            float bv = -1.0f; int bi = 0x7fffffff;
            for (int i = tid; i < NPART; i += 256) better(s_pv[i], s_pi[i], bv, bi);
            #pragma unroll
            for (int off = 16; off; off >>= 1) {
                float ov = __shfl_down_sync(0xffffffffu, bv, off);
                int   oi = __shfl_down_sync(0xffffffffu, bi, off);
                better(ov, oi, bv, bi);
            }
            if (lane == 0) { s_rv[warp] = bv; s_ri[warp] = bi; }
        }
        __syncthreads();
        if (tid == 0) {
            float bv = -1.0f; int bi = 0x7fffffff;
            #pragma unroll
            for (int i = 0; i < 8; i++) better(s_rv[i], s_ri[i], bv, bi);
            s_r = bi / AW; s_c = bi % AW;
        }
        __syncthreads();
        const int r = s_r, c = s_c;

        // ---- B: window max (value = orig unless covered by window j < it)
        if (tid < 25) {
            int y = r + tid / 5, x = c + tid % 5;
            float v = src[y * H + x];
            for (int j = 0; j < it; j++)
                if ((unsigned)(y - s_wr[j]) < 5u && (unsigned)(x - s_wc[j]) < 5u) v = 0.0f;
            s_win[tid] = v;
        }
        __syncthreads();
        if (tid == 0) {
            float mv = -1.0f;
            #pragma unroll
            for (int i = 0; i < 25; i++) mv = fmaxf(mv, s_win[i]);
            s_mv[it] = mv; s_wr[it] = r; s_wc[it] = c;
        }
        __syncthreads();   // s_wr[it]/s_wc[it] visible to all before D

        // ---- D: recompute affected partials (<= 9 rows x <= 2 segs), colsum
        //         rebuilt from src with coverage over windows j <= it.
        {
            const int jlo = max(0, c - 4), jhi = min(AW - 1, c + 4);
            const int s0 = jlo / SEG, s1 = jhi / SEG;
            const int nsegs = s1 - s0 + 1;
            const int r0c = max(0, r - 4), r1c = min(AW - 1, r + 4);
            const int npairs = (r1c - r0c + 1) * nsegs;
            for (int p = warp; p < npairs; p += 8) {
                const int rr = r0c + p / nsegs, sg = s0 + p % nsegs;
                const int c0 = sg * SEG;
                // colsum for cols [c0, c0+125): 5-row sums with zero coverage
                for (int j = lane; j < SEG + 4; j += 32) {
                    const int cc = c0 + j;
                    float s = 0.0f;
                    #pragma unroll
                    for (int d = 0; d < 5; d++) {
                        const int y = rr + d;
                        float v = src[y * H + cc];
                        for (int jj = 0; jj <= it; jj++)
                            if ((unsigned)(y - s_wr[jj]) < 5u &&
                                (unsigned)(cc - s_wc[jj]) < 5u) v = 0.0f;
                        s = s + v;   // left-assoc, matches scan0 ring
                    }
                    s_csbuf[warp][j] = s;
                }
                __syncwarp();
                float bv2 = -1.0f; int bi2 = 0x7fffffff;
                for (int j = lane; j < SEG; j += 32) {
                    const float* rb = s_csbuf[warp];
                    float v = rb[j] + rb[j + 1] + rb[j + 2] + rb[j + 3] + rb[j + 4];
                    better(v, rr * AW + c0 + j, bv2, bi2);
                }
                #pragma unroll
                for (int off = 16; off; off >>= 1) {
                    float ov = __shfl_down_sync(0xffffffffu, bv2, off);
                    int   oi = __shfl_down_sync(0xffffffffu, bi2, off);
                    better(ov, oi, bv2, bi2);
                }
                if (lane == 0) { s_pv[rr * NSEG + sg] = bv2; s_pi[rr * NSEG + sg] = bi2; }
                __syncwarp();
            }
        }
        __syncthreads();
    }

    if (tid < KCL) {
        g_wr[b * KCL + tid] = s_wr[tid];
        g_wc[b * KCL + tid] = s_wc[tid];
        g_maxv[b * KCL + tid] = s_mv[tid];
    }
}

// ---------------------------------------------------------------------------
// eq: single fused first-occurrence pass over the ORIGINAL input for all 6
// max values. Value at scan i is orig unless covered by window j<i (then 0,
// never equal to mv_i > 0). Matches rare -> atomicMin (commutative,
// deterministic). grid (NB, 32).
// ---------------------------------------------------------------------------
__global__ __launch_bounds__(256)
void eq_kernel(const float* __restrict__ in) {
    const int b = blockIdx.x, cb = blockIdx.y, tid = threadIdx.x;

    __shared__ float s_mv[KCL];
    __shared__ int   s_wr[KCL], s_wc[KCL];
    __shared__ float s_lo;

    if (tid < KCL) {
        s_mv[tid] = g_maxv[b * KCL + tid];
        s_wr[tid] = g_wr[b * KCL + tid];
        s_wc[tid] = g_wc[b * KCL + tid];
    }
    __syncthreads();
    if (tid == 0) {
        float lo = s_mv[0];
        #pragma unroll
        for (int i = 1; i < KCL; i++) lo = fminf(lo, s_mv[i]);
        s_lo = lo;
    }
    __syncthreads();
    const float lo = s_lo;

    const float4* h4 = (const float4*)(in + (size_t)b * H * H);
    const int b0 = cb * CE4, e0 = min(NE4, b0 + CE4);
    for (int t4 = b0 + tid; t4 < e0; t4 += 256) {
        float4 v = h4[t4];
        float m4 = fmaxf(fmaxf(v.x, v.y), fmaxf(v.z, v.w));
        if (m4 < lo) continue;                       // fast path
        #pragma unroll
        for (int u = 0; u < 4; u++) {
            float val = (u == 0) ? v.x : (u == 1) ? v.y : (u == 2) ? v.z : v.w;
            int id = t4 * 4 + u;
            #pragma unroll
            for (int i = 0; i < KCL; i++) {
                if (val == s_mv[i]) {
                    int y = id / H, x = id - y * H;
                    bool cov = false;
                    for (int j = 0; j < i; j++)
                        if ((unsigned)(y - s_wr[j]) < 5u && (unsigned)(x - s_wc[j]) < 5u) cov = true;
                    if (!cov) atomicMin(&g_eqmin[b * KCL + i], id);
                }
            }
        }
    }
}

// ---------------------------------------------------------------------------
// refine: 4 warps per cluster (768 thr) mean shift (THR=12 -> 26x26 bbox,
// w = hm*m/d^2), then rounding + clamped 4x4 confidence on ORIGINAL heatmap.
// Deterministic: warp shuffles + fixed-order 4-partial sums.
// ---------------------------------------------------------------------------
__global__ __launch_bounds__(768)
void refine_kernel(const float* __restrict__ in, float* __restrict__ out) {
    const int b = blockIdx.x, tid = threadIdx.x;
    const int wid = tid >> 5, lane = tid & 31;
    const int k = wid >> 2, sw = wid & 3;   // cluster, sub-warp
    const float* hm = in + (size_t)b * H * H;

    __shared__ float cly[KCL], clx[KCL];
    __shared__ float pY[KCL][RW], pX[KCL][RW], pW[KCL][RW];

    if (tid < KCL) {
        int fh = g_eqmin[b * KCL + tid];
        cly[tid] = (float)(fh / H);
        clx[tid] = (float)(fh % H);
    }
    __syncthreads();

    for (int it = 0; it < ITERS; it++) {
        {
            float cy = cly[k], cx = clx[k];
            int y0 = max(0, (int)floorf(cy - 12.0f));
            int y1 = min(H - 1, (int)ceilf(cy + 12.0f));
            int x0 = max(0, (int)floorf(cx - 12.0f));
            int x1 = min(H - 1, (int)ceilf(cx + 12.0f));
            int w  = x1 - x0 + 1;
            int nb = (y1 - y0 + 1) * w;

            float sy = 0.0f, sx = 0.0f, swt = 0.0f;
            for (int t = sw * 32 + lane; t < nb; t += 128) {
                int y = y0 + t / w;
                int x = x0 + t % w;
                float dy = (float)y - cy, dx = (float)x - cx;
                float d2 = fmaxf(dy * dy + dx * dx, 1e-6f);
                if (d2 < 144.0f) {
                    float m2 = d2;
                    #pragma unroll
                    for (int k2 = 0; k2 < KCL; k2++) {
                        float ey = (float)y - cly[k2], ex = (float)x - clx[k2];
                        m2 = fminf(m2, fmaxf(ey * ey + ex * ex, 1e-6f));
                    }
                    float wgt = hm[y * H + x] * sqrtf(m2) / d2;
                    sy += wgt * (float)y;
                    sx += wgt * (float)x;
                    swt += wgt;
                }
            }
            #pragma unroll
            for (int off = 16; off; off >>= 1) {
                sy  += __shfl_down_sync(0xffffffffu, sy, off);
                sx  += __shfl_down_sync(0xffffffffu, sx, off);
                swt += __shfl_down_sync(0xffffffffu, swt, off);
            }
            if (lane == 0) { pY[k][sw] = sy; pX[k][sw] = sx; pW[k][sw] = swt; }
        }
        __syncthreads();
        if (tid < KCL) {
            float ay = 0.0f, ax = 0.0f, aw = 0.0f;
            #pragma unroll
            for (int i = 0; i < RW; i++) { ay += pY[tid][i]; ax += pX[tid][i]; aw += pW[tid][i]; }
            cly[tid] = ay / aw;
            clx[tid] = ax / aw;
        }
        __syncthreads();
    }

    if (tid < KCL) {
        int iy = (int)rintf(cly[tid]);   // round-half-to-even == jnp.round
        int ix = (int)rintf(clx[tid]);
        out[(b * KCL + tid) * 2 + 0] = (float)iy;
        out[(b * KCL + tid) * 2 + 1] = (float)ix;
        int sy0 = min(max(iy - 2, 0), H - 4);   // dynamic_slice clamp
        int sx0 = min(max(ix - 2, 0), H - 4);
        float cf = 0.0f;
        #pragma unroll
        for (int di = 0; di < 4; di++)
            #pragma unroll
            for (int dj = 0; dj < 4; dj++)
                cf += hm[(sy0 + di) * H + (sx0 + dj)];
        out[NB * KCL * 2 + b * KCL + tid] = cf;
    }
}

extern "C" void kernel_launch(void* const* d_in, const int* in_sizes, int n_in,
                              void* d_out, int out_size) {
    const float* hm = (const float*)d_in[0];
    float* out = (float*)d_out;

    scan0_kernel<<<dim3(NB, NCH0), 256>>>(hm);
    final6_kernel<<<NB, 256>>>(hm);
    eq_kernel<<<dim3(NB, NCHE), 256>>>(hm);
    refine_kernel<<<NB, 768>>>(hm, out);
}

// round 5
// speedup vs baseline: 1.0151x; 1.0151x over previous
#include <cuda_runtime.h>
#include <cuda_bf16.h>

#define H      488
#define AW     484          // H - 5 + 1
#define KCL    6
#define NB     32
#define ITERS  10
#define SEG    121          // 484 = 4 * 121 windows per row
#define NSEG   4
#define NPART  (AW * NSEG)  // 1936 partials per batch
#define CR0    16           // rows per scan0 chunk
#define NCH0   31           // ceil(484/16)
#define NE4    (H * H / 4)  // 59536 float4 per batch
#define RW     4            // warps per cluster in refine

// Scratch (allocation-free: __device__ globals)
__device__ float g_colsum[NB * AW * H];     // vertical 5-sums
__device__ float g_pv[NB * NPART];          // per-(row,seg) argmax value
__device__ int   g_pi[NB * NPART];          // per-(row,seg) argmax flat window idx
__device__ int   g_wr[NB * KCL], g_wc[NB * KCL];
__device__ float g_maxv[NB * KCL];

__device__ __forceinline__ void better(float v, int i, float& bv, int& bi) {
    if (v > bv || (v == bv && i < bi)) { bv = v; bi = i; }
}

// ---------------------------------------------------------------------------
// scan0: input -> colsum (global) + initial argmax partials. grid (NB, 31).
// ---------------------------------------------------------------------------
__global__ __launch_bounds__(256)
void scan0_kernel(const float* __restrict__ in) {
    const int b = blockIdx.x, cb = blockIdx.y, tid = threadIdx.x;
    const float* src = in + (size_t)b * H * H;
    float* cs = g_colsum + (size_t)b * AW * H;

    __shared__ float s_cs[CR0][H];

    const int R0 = CR0 * cb, R1 = min(AW, R0 + CR0);

    // column 5-sums for rows [R0, R1): left-assoc register ring
    for (int j = tid; j < H; j += 256) {
        float w0 = src[(R0 + 0) * H + j], w1 = src[(R0 + 1) * H + j],
              w2 = src[(R0 + 2) * H + j], w3 = src[(R0 + 3) * H + j], w4;
        for (int i = R0; i < R1; i++) {
            w4 = src[(i + 4) * H + j];
            float s = w0 + w1 + w2 + w3 + w4;
            s_cs[i - R0][j] = s;
            cs[i * H + j] = s;
            w0 = w1; w1 = w2; w2 = w3; w3 = w4;
        }
    }
    __syncthreads();

    // partials: 64 (row,seg) pairs, 4 sub-threads each
    const int pair = tid >> 2, sub = tid & 3;
    const int lr = pair >> 2, sg = pair & 3;
    const int nrows = R1 - R0;

    float bv = -1.0f; int bi = 0x7fffffff;
    if (lr < nrows) {
        const float* row = s_cs[lr];
        const int jbeg = sg * SEG;
        for (int j = jbeg + sub; j < jbeg + SEG; j += 4) {
            float v = row[j] + row[j + 1] + row[j + 2] + row[j + 3] + row[j + 4];
            better(v, (R0 + lr) * AW + j, bv, bi);
        }
    }
    #pragma unroll
    for (int off = 2; off; off >>= 1) {
        float ov = __shfl_down_sync(0xffffffffu, bv, off);
        int   oi = __shfl_down_sync(0xffffffffu, bi, off);
        better(ov, oi, bv, bi);
    }
    if (sub == 0 && lr < nrows) {
        g_pv[b * NPART + (R0 + lr) * NSEG + sg] = bv;
        g_pi[b * NPART + (R0 + lr) * NSEG + sg] = bi;
    }
}

// ---------------------------------------------------------------------------
// final6: all 6 greedy extractions. grid NB x 512. Partials in smem; colsum
// repaired incrementally (<=45 entries) from src with window coverage.
// ---------------------------------------------------------------------------
__global__ __launch_bounds__(512)
void final6_kernel(const float* __restrict__ in) {
    const int b = blockIdx.x, tid = threadIdx.x;
    const int warp = tid >> 5, lane = tid & 31;
    const float* src = in + (size_t)b * H * H;
    float* cs = g_colsum + (size_t)b * AW * H;

    __shared__ float s_pv[NPART];
    __shared__ int   s_pi[NPART];
    __shared__ float s_rv[16];
    __shared__ int   s_ri[16];
    __shared__ float s_win[25];
    __shared__ int   s_wr[KCL], s_wc[KCL];
    __shared__ float s_mv[KCL];
    __shared__ int   s_r, s_c;

    for (int i = tid; i < NPART; i += 512) {
        s_pv[i] = g_pv[b * NPART + i];
        s_pi[i] = g_pi[b * NPART + i];
    }
    __syncthreads();

    for (int it = 0; it < KCL; it++) {
        // ---- A: global argmax over 1936 smem partials (shuffle tree)
        {
            float bv = -1.0f; int bi = 0x7fffffff;
            for (int i = tid; i < NPART; i += 512) better(s_pv[i], s_pi[i], bv, bi);
            #pragma unroll
            for (int off = 16; off; off >>= 1) {
                float ov = __shfl_down_sync(0xffffffffu, bv, off);
                int   oi = __shfl_down_sync(0xffffffffu, bi, off);
                better(ov, oi, bv, bi);
            }
            if (lane == 0) { s_rv[warp] = bv; s_ri[warp] = bi; }
        }
        __syncthreads();
        if (tid == 0) {
            float bv = -1.0f; int bi = 0x7fffffff;
            #pragma unroll
            for (int i = 0; i < 16; i++) better(s_rv[i], s_ri[i], bv, bi);
            s_r = bi / AW; s_c = bi % AW;
        }
        __syncthreads();
        const int r = s_r, c = s_c;

        // ---- B: window max (value = orig unless covered by window j < it)
        if (tid < 25) {
            int y = r + tid / 5, x = c + tid % 5;
            float v = src[y * H + x];
            for (int j = 0; j < it; j++)
                if ((unsigned)(y - s_wr[j]) < 5u && (unsigned)(x - s_wc[j]) < 5u) v = 0.0f;
            s_win[tid] = v;
        }
        __syncthreads();
        if (tid == 0) {
            float mv = -1.0f;
            #pragma unroll
            for (int i = 0; i < 25; i++) mv = fmaxf(mv, s_win[i]);
            s_mv[it] = mv; s_wr[it] = r; s_wc[it] = c;
        }

        // ---- C: incremental colsum repair (<=45 entries), coverage j <= it
        const int r0c = max(0, r - 4), r1c = min(AW - 1, r + 4);
        {
            int nc = (r1c - r0c + 1) * 5;
            if (tid < nc) {
                int rr = r0c + tid / 5, cc = c + tid % 5;
                float s = 0.0f;
                #pragma unroll
                for (int d = 0; d < 5; d++) {
                    int y = rr + d;
                    float v = src[y * H + cc];
                    if ((unsigned)(y - r) < 5u && (unsigned)(cc - c) < 5u) v = 0.0f;
                    for (int j = 0; j < it; j++)
                        if ((unsigned)(y - s_wr[j]) < 5u && (unsigned)(cc - s_wc[j]) < 5u) v = 0.0f;
                    s = s + v;   // left-assoc, matches scan0 ring
                }
                cs[rr * H + cc] = s;
            }
        }
        __syncthreads();

        // ---- D: recompute affected partials (<= 9 rows x <= 2 segs)
        {
            const int jlo = max(0, c - 4), jhi = min(AW - 1, c + 4);
            const int s0 = jlo / SEG, s1 = jhi / SEG;
            const int nsegs = s1 - s0 + 1;
            const int npairs = (r1c - r0c + 1) * nsegs;
            for (int p = warp; p < npairs; p += 16) {
                int rr = r0c + p / nsegs, sg = s0 + p % nsegs;
                const float* row = cs + rr * H;
                float bv2 = -1.0f; int bi2 = 0x7fffffff;
                for (int j = sg * SEG + lane; j < sg * SEG + SEG; j += 32) {
                    float v = row[j] + row[j + 1] + row[j + 2] + row[j + 3] + row[j + 4];
                    better(v, rr * AW + j, bv2, bi2);
                }
                #pragma unroll
                for (int off = 16; off; off >>= 1) {
                    float ov = __shfl_down_sync(0xffffffffu, bv2, off);
                    int   oi = __shfl_down_sync(0xffffffffu, bi2, off);
                    better(ov, oi, bv2, bi2);
                }
                if (lane == 0) { s_pv[rr * NSEG + sg] = bv2; s_pi[rr * NSEG + sg] = bi2; }
            }
        }
        __syncthreads();
    }

    if (tid < KCL) {
        g_wr[b * KCL + tid] = s_wr[tid];
        g_wc[b * KCL + tid] = s_wc[tid];
        g_maxv[b * KCL + tid] = s_mv[tid];
    }
}

// ---------------------------------------------------------------------------
// refine: fused per-batch (block-local) pipeline:
//   (1) eq: first-occurrence scan of this batch for all 6 max values
//       (value = orig unless covered by earlier window -> 0). Shared
//       atomicMin: commutative -> deterministic.
//   (2) 10 mean-shift iterations, 4 warps/cluster, rows per sub-warp,
//       x per lane (bbox width <= 26 <= 32 -> no integer div/mod).
//       One __syncthreads/iter: every thread redundantly recomputes all 6
//       centers from the 72 smem partials (identical op order).
//   (3) round + clamped 4x4 confidence on the ORIGINAL heatmap.
// ---------------------------------------------------------------------------
__global__ __launch_bounds__(768)
void refine_kernel(const float* __restrict__ in, float* __restrict__ out) {
    const int b = blockIdx.x, tid = threadIdx.x;
    const int wid = tid >> 5, lane = tid & 31;
    const int k = wid >> 2, sw = wid & 3;   // cluster, sub-warp
    const float* hm = in + (size_t)b * H * H;

    __shared__ float s_mv[KCL];
    __shared__ int   s_wr[KCL], s_wc[KCL];
    __shared__ int   s_eq[KCL];
    __shared__ float s_lo;
    __shared__ float pY[KCL][RW], pX[KCL][RW], pW[KCL][RW];

    if (tid < KCL) {
        s_mv[tid] = g_maxv[b * KCL + tid];
        s_wr[tid] = g_wr[b * KCL + tid];
        s_wc[tid] = g_wc[b * KCL + tid];
        s_eq[tid] = 0x7fffffff;
    }
    __syncthreads();
    if (tid == 0) {
        float lo = s_mv[0];
        #pragma unroll
        for (int i = 1; i < KCL; i++) lo = fminf(lo, s_mv[i]);
        s_lo = lo;
    }
    __syncthreads();

    // ---- (1) eq scan over this batch's image
    {
        const float lo = s_lo;
        const float4* h4 = (const float4*)hm;
        for (int t4 = tid; t4 < NE4; t4 += 768) {
            float4 v = h4[t4];
            float m4 = fmaxf(fmaxf(v.x, v.y), fmaxf(v.z, v.w));
            if (m4 < lo) continue;                       // fast path
            #pragma unroll
            for (int u = 0; u < 4; u++) {
                float val = (u == 0) ? v.x : (u == 1) ? v.y : (u == 2) ? v.z : v.w;
                int id = t4 * 4 + u;
                #pragma unroll
                for (int i = 0; i < KCL; i++) {
                    if (val == s_mv[i]) {
                        int y = id / H, x = id - y * H;
                        bool cov = false;
                        for (int j = 0; j < i; j++)
                            if ((unsigned)(y - s_wr[j]) < 5u && (unsigned)(x - s_wc[j]) < 5u) cov = true;
                        if (!cov) atomicMin(&s_eq[i], id);
                    }
                }
            }
        }
    }
    __syncthreads();

    // seed centers in registers (all threads hold all 6)
    float rcy[KCL], rcx[KCL];
    #pragma unroll
    for (int i = 0; i < KCL; i++) {
        int fh = s_eq[i];
        rcy[i] = (float)(fh / H);
        rcx[i] = (float)(fh % H);
    }

    // ---- (2) mean shift
    for (int it = 0; it < ITERS; it++) {
        {
            const float cy = rcy[k], cx = rcx[k];
            const int y0 = max(0, (int)floorf(cy - 12.0f));
            const int y1 = min(H - 1, (int)ceilf(cy + 12.0f));
            const int x0 = max(0, (int)floorf(cx - 12.0f));
            const int x1 = min(H - 1, (int)ceilf(cx + 12.0f));
            const int w  = x1 - x0 + 1;        // <= 26 <= 32 lanes

            float sy = 0.0f, sx = 0.0f, swt = 0.0f;
            const int x = x0 + lane;
            if (lane < w) {
                const float dx = (float)x - cx;
                for (int y = y0 + sw; y <= y1; y += RW) {
                    float dy = (float)y - cy;
                    float d2 = fmaxf(dy * dy + dx * dx, 1e-6f);
                    if (d2 < 144.0f) {
                        float m2 = d2;
                        #pragma unroll
                        for (int k2 = 0; k2 < KCL; k2++) {
                            float ey = (float)y - rcy[k2], ex = (float)x - rcx[k2];
                            m2 = fminf(m2, fmaxf(ey * ey + ex * ex, 1e-6f));
                        }
                        float wgt = hm[y * H + x] * sqrtf(m2) / d2;
                        sy += wgt * (float)y;
                        sx += wgt * (float)x;
                        swt += wgt;
                    }
                }
            }
            #pragma unroll
            for (int off = 16; off; off >>= 1) {
                sy  += __shfl_down_sync(0xffffffffu, sy, off);
                sx  += __shfl_down_sync(0xffffffffu, sx, off);
                swt += __shfl_down_sync(0xffffffffu, swt, off);
            }
            if (lane == 0) { pY[k][sw] = sy; pX[k][sw] = sx; pW[k][sw] = swt; }
        }
        __syncthreads();
        // every thread recomputes all centers identically (deterministic)
        #pragma unroll
        for (int k2 = 0; k2 < KCL; k2++) {
            float ay = pY[k2][0] + pY[k2][1] + pY[k2][2] + pY[k2][3];
            float ax = pX[k2][0] + pX[k2][1] + pX[k2][2] + pX[k2][3];
            float aw = pW[k2][0] + pW[k2][1] + pW[k2][2] + pW[k2][3];
            rcy[k2] = ay / aw;
            rcx[k2] = ax / aw;
        }
        __syncthreads();   // protect pY/pX/pW reuse next iteration
    }

    // ---- (3) outputs
    if (tid < KCL) {
        int iy = (int)rintf(rcy[tid]);   // round-half-to-even == jnp.round
        int ix = (int)rintf(rcx[tid]);
        out[(b * KCL + tid) * 2 + 0] = (float)iy;
        out[(b * KCL + tid) * 2 + 1] = (float)ix;
        int sy0 = min(max(iy - 2, 0), H - 4);   // dynamic_slice clamp
        int sx0 = min(max(ix - 2, 0), H - 4);
        float cf = 0.0f;
        #pragma unroll
        for (int di = 0; di < 4; di++)
            #pragma unroll
            for (int dj = 0; dj < 4; dj++)
                cf += hm[(sy0 + di) * H + (sx0 + dj)];
        out[NB * KCL * 2 + b * KCL + tid] = cf;
    }
}

extern "C" void kernel_launch(void* const* d_in, const int* in_sizes, int n_in,
                              void* d_out, int out_size) {
    const float* hm = (const float*)d_in[0];
    float* out = (float*)d_out;

    scan0_kernel<<<dim3(NB, NCH0), 256>>>(hm);
    final6_kernel<<<NB, 512>>>(hm);
    refine_kernel<<<NB, 768>>>(hm, out);
}

// round 6
// speedup vs baseline: 1.4668x; 1.4449x over previous
#include <cuda_runtime.h>
#include <cuda_bf16.h>

#define H      488
#define AW     484          // H - 5 + 1
#define KCL    6
#define NB     32
#define ITERS  10
#define SEG    121          // 484 = 4 * 121 windows per row
#define NSEG   4
#define NPART  (AW * NSEG)  // 1936 partials per batch
#define CR0    8            // rows per scan0 chunk
#define NCH0   61           // ceil(484/8)
#define NE4    (H * H / 4)  // 59536 uint4/float4 per batch
#define RW     5            // warps per cluster in refine (30 of 32 warps)

// Scratch (allocation-free: __device__ globals)
__device__ float g_colsum[NB * AW * H];     // vertical 5-sums
__device__ float g_pv[NB * NPART];          // per-(row,seg) argmax value
__device__ int   g_pi[NB * NPART];          // per-(row,seg) argmax flat window idx

__device__ __forceinline__ void better(float v, int i, float& bv, int& bi) {
    if (v > bv || (v == bv && i < bi)) { bv = v; bi = i; }
}

// ---------------------------------------------------------------------------
// scan0: input -> colsum (global, float4) + initial argmax partials.
// grid (NB, 61) x 128. 8 rows per chunk, 4 cols per thread (vectorized).
// ---------------------------------------------------------------------------
__global__ __launch_bounds__(128)
void scan0_kernel(const float* __restrict__ in) {
    const int b = blockIdx.x, cb = blockIdx.y, tid = threadIdx.x;
    const float* src = in + (size_t)b * H * H;
    float* cs = g_colsum + (size_t)b * AW * H;

    __shared__ float s_cs[CR0][H];

    const int R0 = CR0 * cb, R1 = min(AW, R0 + CR0);

    // column 5-sums, 4 columns per thread via float4 (left-assoc per column)
    if (tid < H / 4) {
        const float4* s4 = (const float4*)src;
        float4* c4 = (float4*)cs;
        const int HQ = H / 4;                 // 122 float4 per row
        float4 w0 = s4[(R0 + 0) * HQ + tid], w1 = s4[(R0 + 1) * HQ + tid],
               w2 = s4[(R0 + 2) * HQ + tid], w3 = s4[(R0 + 3) * HQ + tid], w4;
        for (int i = R0; i < R1; i++) {
            w4 = s4[(i + 4) * HQ + tid];
            float4 s;
            s.x = w0.x + w1.x + w2.x + w3.x + w4.x;
            s.y = w0.y + w1.y + w2.y + w3.y + w4.y;
            s.z = w0.z + w1.z + w2.z + w3.z + w4.z;
            s.w = w0.w + w1.w + w2.w + w3.w + w4.w;
            *(float4*)&s_cs[i - R0][tid * 4] = s;
            c4[i * HQ + tid] = s;
            w0 = w1; w1 = w2; w2 = w3; w3 = w4;
        }
    }
    __syncthreads();

    // partials: up to 32 (row,seg) pairs, 4 sub-threads each
    const int pair = tid >> 2, sub = tid & 3;
    const int lr = pair >> 2, sg = pair & 3;
    const int nrows = R1 - R0;

    float bv = -1.0f; int bi = 0x7fffffff;
    if (lr < nrows) {
        const float* row = s_cs[lr];
        const int jbeg = sg * SEG;
        for (int j = jbeg + sub; j < jbeg + SEG; j += 4) {
            float v = row[j] + row[j + 1] + row[j + 2] + row[j + 3] + row[j + 4];
            better(v, (R0 + lr) * AW + j, bv, bi);
        }
    }
    #pragma unroll
    for (int off = 2; off; off >>= 1) {
        float ov = __shfl_down_sync(0xffffffffu, bv, off);
        int   oi = __shfl_down_sync(0xffffffffu, bi, off);
        better(ov, oi, bv, bi);
    }
    if (sub == 0 && lr < nrows) {
        g_pv[b * NPART + (R0 + lr) * NSEG + sg] = bv;
        g_pi[b * NPART + (R0 + lr) * NSEG + sg] = bi;
    }
}

// ---------------------------------------------------------------------------
// solve: one block per batch (1024 thr). Fused:
//   (I)   6 greedy extractions (smem partials, incremental colsum repair)
//   (II)  branchless-int first-occurrence scan for all 6 window maxima
//   (III) 10 mean-shift iterations (5 warps/cluster; centers in smem-free
//         registers, warp's own center via uniform select chain)
//   (IV)  round + clamped 4x4 confidence windows on the ORIGINAL heatmap
// ---------------------------------------------------------------------------
__global__ __launch_bounds__(1024)
void solve_kernel(const float* __restrict__ in, float* __restrict__ out) {
    const int b = blockIdx.x, tid = threadIdx.x;
    const int warp = tid >> 5, lane = tid & 31;
    const float* src = in + (size_t)b * H * H;
    float* cs = g_colsum + (size_t)b * AW * H;

    __shared__ float s_pv[NPART];
    __shared__ int   s_pi[NPART];
    __shared__ float s_rv[32];
    __shared__ int   s_ri[32];
    __shared__ float s_win[25];
    __shared__ int   s_wr[KCL], s_wc[KCL];
    __shared__ float s_mv[KCL];
    __shared__ int   s_r, s_c;
    __shared__ int   s_eq[KCL];
    __shared__ float pY[KCL][RW], pX[KCL][RW], pW[KCL][RW];

    for (int i = tid; i < NPART; i += 1024) {
        s_pv[i] = g_pv[b * NPART + i];
        s_pi[i] = g_pi[b * NPART + i];
    }
    if (tid < KCL) s_eq[tid] = 0x7fffffff;
    __syncthreads();

    // ==================== (I) greedy extractions ====================
    for (int it = 0; it < KCL; it++) {
        // A: argmax over 1936 smem partials (shuffle tree)
        {
            float bv = -1.0f; int bi = 0x7fffffff;
            for (int i = tid; i < NPART; i += 1024) better(s_pv[i], s_pi[i], bv, bi);
            #pragma unroll
            for (int off = 16; off; off >>= 1) {
                float ov = __shfl_down_sync(0xffffffffu, bv, off);
                int   oi = __shfl_down_sync(0xffffffffu, bi, off);
                better(ov, oi, bv, bi);
            }
            if (lane == 0) { s_rv[warp] = bv; s_ri[warp] = bi; }
        }
        __syncthreads();
        if (tid == 0) {
            float bv = -1.0f; int bi = 0x7fffffff;
            #pragma unroll
            for (int i = 0; i < 32; i++) better(s_rv[i], s_ri[i], bv, bi);
            s_r = bi / AW; s_c = bi % AW;
        }
        __syncthreads();
        const int r = s_r, c = s_c;

        // B: window max (value = orig unless covered by window j < it)
        if (tid < 25) {
            int y = r + tid / 5, x = c + tid % 5;
            float v = src[y * H + x];
            for (int j = 0; j < it; j++)
                if ((unsigned)(y - s_wr[j]) < 5u && (unsigned)(x - s_wc[j]) < 5u) v = 0.0f;
            s_win[tid] = v;
        }
        __syncthreads();
        if (tid == 0) {
            float mv = -1.0f;
            #pragma unroll
            for (int i = 0; i < 25; i++) mv = fmaxf(mv, s_win[i]);
            s_mv[it] = mv; s_wr[it] = r; s_wc[it] = c;
        }

        // C: incremental colsum repair (<=45 entries), coverage j <= it
        const int r0c = max(0, r - 4), r1c = min(AW - 1, r + 4);
        {
            int nc = (r1c - r0c + 1) * 5;
            if (tid < nc) {
                int rr = r0c + tid / 5, cc = c + tid % 5;
                float s = 0.0f;
                #pragma unroll
                for (int d = 0; d < 5; d++) {
                    int y = rr + d;
                    float v = src[y * H + cc];
                    if ((unsigned)(y - r) < 5u && (unsigned)(cc - c) < 5u) v = 0.0f;
                    for (int j = 0; j < it; j++)
                        if ((unsigned)(y - s_wr[j]) < 5u && (unsigned)(cc - s_wc[j]) < 5u) v = 0.0f;
                    s = s + v;   // left-assoc, matches scan0 ring
                }
                cs[rr * H + cc] = s;
            }
        }
        __syncthreads();

        // D: recompute affected partials (<= 9 rows x <= 2 segs)
        {
            const int jlo = max(0, c - 4), jhi = min(AW - 1, c + 4);
            const int s0 = jlo / SEG, s1 = jhi / SEG;
            const int nsegs = s1 - s0 + 1;
            const int npairs = (r1c - r0c + 1) * nsegs;
            for (int p = warp; p < npairs; p += 32) {
                int rr = r0c + p / nsegs, sg = s0 + p % nsegs;
                const float* row = cs + rr * H;
                float bv2 = -1.0f; int bi2 = 0x7fffffff;
                for (int j = sg * SEG + lane; j < sg * SEG + SEG; j += 32) {
                    float v = row[j] + row[j + 1] + row[j + 2] + row[j + 3] + row[j + 4];
                    better(v, rr * AW + j, bv2, bi2);
                }
                #pragma unroll
                for (int off = 16; off; off >>= 1) {
                    float ov = __shfl_down_sync(0xffffffffu, bv2, off);
                    int   oi = __shfl_down_sync(0xffffffffu, bi2, off);
                    better(ov, oi, bv2, bi2);
                }
                if (lane == 0) { s_pv[rr * NSEG + sg] = bv2; s_pi[rr * NSEG + sg] = bi2; }
            }
        }
        __syncthreads();
    }

    // ==================== (II) first-occurrence eq scan ====================
    // positive finite floats: float equality <=> bit equality. Branchless
    // 24-compare filter per uint4; rare slow path; shared atomicMin (min is
    // commutative -> deterministic).
    {
        unsigned p0 = __float_as_uint(s_mv[0]), p1 = __float_as_uint(s_mv[1]),
                 p2 = __float_as_uint(s_mv[2]), p3 = __float_as_uint(s_mv[3]),
                 p4 = __float_as_uint(s_mv[4]), p5 = __float_as_uint(s_mv[5]);
        const uint4* h4 = (const uint4*)src;
        for (int t4 = tid; t4 < NE4; t4 += 1024) {
            uint4 v = h4[t4];
            bool hit =
                (v.x == p0) | (v.y == p0) | (v.z == p0) | (v.w == p0) |
                (v.x == p1) | (v.y == p1) | (v.z == p1) | (v.w == p1) |
                (v.x == p2) | (v.y == p2) | (v.z == p2) | (v.w == p2) |
                (v.x == p3) | (v.y == p3) | (v.z == p3) | (v.w == p3) |
                (v.x == p4) | (v.y == p4) | (v.z == p4) | (v.w == p4) |
                (v.x == p5) | (v.y == p5) | (v.z == p5) | (v.w == p5);
            if (!hit) continue;
            #pragma unroll
            for (int u = 0; u < 4; u++) {
                unsigned val = (u == 0) ? v.x : (u == 1) ? v.y : (u == 2) ? v.z : v.w;
                int id = t4 * 4 + u;
                #pragma unroll
                for (int i = 0; i < KCL; i++) {
                    unsigned pi2 = (i == 0) ? p0 : (i == 1) ? p1 : (i == 2) ? p2
                                 : (i == 3) ? p3 : (i == 4) ? p4 : p5;
                    if (val == pi2) {
                        int y = id / H, x = id - y * H;
                        bool cov = false;
                        for (int j = 0; j < i; j++)
                            if ((unsigned)(y - s_wr[j]) < 5u && (unsigned)(x - s_wc[j]) < 5u) cov = true;
                        if (!cov) atomicMin(&s_eq[i], id);
                    }
                }
            }
        }
    }
    __syncthreads();

    // ==================== (III) mean shift ====================
    // centers: register array with CONSTANT indexing only; the warp's own
    // center comes from a uniform select chain (k is warp-uniform).
    float rcy[KCL], rcx[KCL];
    #pragma unroll
    for (int i = 0; i < KCL; i++) {
        int fh = s_eq[i];
        rcy[i] = (float)(fh / H);
        rcx[i] = (float)(fh % H);
    }

    const int k = warp / RW;            // 0..5 for warps 0..29; warps 30,31 idle
    const int sw = warp - k * RW;
    const bool active = (warp < KCL * RW);

    for (int it = 0; it < ITERS; it++) {
        if (active) {
            float cy = rcy[0], cx = rcx[0];
            if (k == 1) { cy = rcy[1]; cx = rcx[1]; }
            if (k == 2) { cy = rcy[2]; cx = rcx[2]; }
            if (k == 3) { cy = rcy[3]; cx = rcx[3]; }
            if (k == 4) { cy = rcy[4]; cx = rcx[4]; }
            if (k == 5) { cy = rcy[5]; cx = rcx[5]; }

            const int y0 = max(0, (int)floorf(cy - 12.0f));
            const int y1 = min(H - 1, (int)ceilf(cy + 12.0f));
            const int x0 = max(0, (int)floorf(cx - 12.0f));
            const int x1 = min(H - 1, (int)ceilf(cx + 12.0f));
            const int w  = x1 - x0 + 1;        // <= 26 <= 32 lanes

            float sy = 0.0f, sx = 0.0f, swt = 0.0f;
            const int x = x0 + lane;
            if (lane < w) {
                const float fx = (float)x;
                const float dx = fx - cx;
                for (int y = y0 + sw; y <= y1; y += RW) {
                    float fy = (float)y;
                    float dy = fy - cy;
                    float d2 = fmaxf(dy * dy + dx * dx, 1e-6f);
                    if (d2 < 144.0f) {
                        float m2 = d2;
                        #pragma unroll
                        for (int k2 = 0; k2 < KCL; k2++) {
                            float ey = fy - rcy[k2], ex = fx - rcx[k2];
                            m2 = fminf(m2, fmaxf(ey * ey + ex * ex, 1e-6f));
                        }
                        float wgt = src[y * H + x] * sqrtf(m2) / d2;
                        sy += wgt * fy;
                        sx += wgt * fx;
                        swt += wgt;
                    }
                }
            }
            #pragma unroll
            for (int off = 16; off; off >>= 1) {
                sy  += __shfl_down_sync(0xffffffffu, sy, off);
                sx  += __shfl_down_sync(0xffffffffu, sx, off);
                swt += __shfl_down_sync(0xffffffffu, swt, off);
            }
            if (lane == 0) { pY[k][sw] = sy; pX[k][sw] = sx; pW[k][sw] = swt; }
        }
        __syncthreads();
        // every thread recomputes all centers identically (constant indices)
        #pragma unroll
        for (int k2 = 0; k2 < KCL; k2++) {
            float ay = pY[k2][0] + pY[k2][1] + pY[k2][2] + pY[k2][3] + pY[k2][4];
            float ax = pX[k2][0] + pX[k2][1] + pX[k2][2] + pX[k2][3] + pX[k2][4];
            float aw = pW[k2][0] + pW[k2][1] + pW[k2][2] + pW[k2][3] + pW[k2][4];
            rcy[k2] = ay / aw;
            rcx[k2] = ax / aw;
        }
        __syncthreads();   // protect pY/pX/pW reuse next iteration
    }

    // ==================== (IV) outputs ====================
    if (tid < KCL) {
        float fy = rcy[0], fx = rcx[0];
        if (tid == 1) { fy = rcy[1]; fx = rcx[1]; }
        if (tid == 2) { fy = rcy[2]; fx = rcx[2]; }
        if (tid == 3) { fy = rcy[3]; fx = rcx[3]; }
        if (tid == 4) { fy = rcy[4]; fx = rcx[4]; }
        if (tid == 5) { fy = rcy[5]; fx = rcx[5]; }
        int iy = (int)rintf(fy);   // round-half-to-even == jnp.round
        int ix = (int)rintf(fx);
        out[(b * KCL + tid) * 2 + 0] = (float)iy;
        out[(b * KCL + tid) * 2 + 1] = (float)ix;
        int sy0 = min(max(iy - 2, 0), H - 4);   // dynamic_slice clamp
        int sx0 = min(max(ix - 2, 0), H - 4);
        float cf = 0.0f;
        #pragma unroll
        for (int di = 0; di < 4; di++)
            #pragma unroll
            for (int dj = 0; dj < 4; dj++)
                cf += src[(sy0 + di) * H + (sx0 + dj)];
        out[NB * KCL * 2 + b * KCL + tid] = cf;
    }
}

extern "C" void kernel_launch(void* const* d_in, const int* in_sizes, int n_in,
                              void* d_out, int out_size) {
    const float* hm = (const float*)d_in[0];
    float* out = (float*)d_out;

    scan0_kernel<<<dim3(NB, NCH0), 128>>>(hm);
    solve_kernel<<<NB, 1024>>>(hm, out);
}